// round 1
// baseline (speedup 1.0000x reference)
#include <cuda_runtime.h>
#include <cuda_bf16.h>
#include <cstdint>

#define N 4096
#define D 512
#define NN ((size_t)N * (size_t)N)
#define OUT_P 1
#define OUT_C (1 + 16777216)

// ---- device scratch (no allocations allowed) ----
__device__ __nv_bfloat16 g_Kb[NN];        // 32 MB bf16 Gibbs kernel (L2-resident)
__device__ float g_zp[128 * N];           // deterministic column-sum partials (2 MB)
__device__ float g_sn[N], g_tn[N];        // row norms of S and T
__device__ float g_u[N], g_v[N];          // Sinkhorn scalings
__device__ float g_part[N];               // per-row loss partials

__device__ __forceinline__ uint32_t f2tf32(float x) {
    uint32_t r;
    asm("cvt.rna.tf32.f32 %0, %1;" : "=r"(r) : "f"(x));
    return r;
}

__device__ __forceinline__ void mma8(float* c, const uint32_t* a, const uint32_t* b) {
    asm volatile(
        "mma.sync.aligned.m16n8k8.row.col.f32.tf32.tf32.f32 "
        "{%0,%1,%2,%3},{%4,%5,%6,%7},{%8,%9},{%0,%1,%2,%3};"
        : "+f"(c[0]), "+f"(c[1]), "+f"(c[2]), "+f"(c[3])
        : "r"(a[0]), "r"(a[1]), "r"(a[2]), "r"(a[3]), "r"(b[0]), "r"(b[1]));
}

// ---- init: v0 = 1 (everything else is recomputed every replay) ----
__global__ void init_kernel() {
    int i = blockIdx.x * blockDim.x + threadIdx.x;
    if (i < N) g_v[i] = 1.0f;
}

// ---- row norms: one warp per row; blocks 0..1023, 8 warps each -> 8192 rows (S then T) ----
__global__ void norms_kernel(const float* __restrict__ S, const float* __restrict__ Tm) {
    int w = blockIdx.x * 8 + (threadIdx.x >> 5);
    int lane = threadIdx.x & 31;
    const float* src = (w < N) ? (S + (size_t)w * D) : (Tm + (size_t)(w - N) * D);
    float s = 0.f;
#pragma unroll
    for (int c = 0; c < 4; c++) {
        float4 a = *(const float4*)(src + c * 128 + lane * 4);
        s += a.x * a.x + a.y * a.y + a.z * a.z + a.w * a.w;
    }
#pragma unroll
    for (int o = 16; o > 0; o >>= 1) s += __shfl_xor_sync(0xffffffffu, s, o);
    if (lane == 0) {
        if (w < N) g_sn[w] = s;
        else       g_tn[w - N] = s;
    }
}

// ---- TF32 tensor-core GEMM + epilogue: C = sqrt(max(sn+tn-2*dot,0)); K = exp(-C/8) ----
// 128x128 block tile, 8 warps (2x4), warp tile 64x32, k-chunk 32.
__global__ void __launch_bounds__(256) gemm_kernel(const float* __restrict__ S,
                                                   const float* __restrict__ Tm,
                                                   float* __restrict__ out) {
    __shared__ float As[128 * 36];   // stride-36 padding: conflict-free frags + 16B-aligned stores
    __shared__ float Bs[128 * 36];
    const int tid  = threadIdx.x;
    const int lane = tid & 31, warp = tid >> 5;
    const int wm = warp & 1, wn = warp >> 1;
    const int bi = blockIdx.y, bj = blockIdx.x;

    float acc[4][4][4];
#pragma unroll
    for (int a = 0; a < 4; a++)
#pragma unroll
        for (int b = 0; b < 4; b++)
#pragma unroll
            for (int r = 0; r < 4; r++) acc[a][b][r] = 0.f;

    for (int kc = 0; kc < D; kc += 32) {
#pragma unroll
        for (int q = 0; q < 4; q++) {
            int f = tid + 256 * q;
            int r = f >> 3, kg = f & 7;
            float4 a = *(const float4*)(S  + (size_t)(bi * 128 + r) * D + kc + kg * 4);
            float4 b = *(const float4*)(Tm + (size_t)(bj * 128 + r) * D + kc + kg * 4);
            float4 at, bt;
            at.x = __uint_as_float(f2tf32(a.x)); at.y = __uint_as_float(f2tf32(a.y));
            at.z = __uint_as_float(f2tf32(a.z)); at.w = __uint_as_float(f2tf32(a.w));
            bt.x = __uint_as_float(f2tf32(b.x)); bt.y = __uint_as_float(f2tf32(b.y));
            bt.z = __uint_as_float(f2tf32(b.z)); bt.w = __uint_as_float(f2tf32(b.w));
            *(float4*)&As[r * 36 + kg * 4] = at;
            *(float4*)&Bs[r * 36 + kg * 4] = bt;
        }
        __syncthreads();
#pragma unroll
        for (int k8 = 0; k8 < 4; k8++) {
            int k0 = k8 * 8 + (lane & 3);
            uint32_t aF[4][4], bF[4][2];
#pragma unroll
            for (int mi = 0; mi < 4; mi++) {
                int row = wm * 64 + mi * 16 + (lane >> 2);
                aF[mi][0] = __float_as_uint(As[row * 36 + k0]);
                aF[mi][1] = __float_as_uint(As[(row + 8) * 36 + k0]);
                aF[mi][2] = __float_as_uint(As[row * 36 + k0 + 4]);
                aF[mi][3] = __float_as_uint(As[(row + 8) * 36 + k0 + 4]);
            }
#pragma unroll
            for (int ni = 0; ni < 4; ni++) {
                int nr = wn * 32 + ni * 8 + (lane >> 2);
                bF[ni][0] = __float_as_uint(Bs[nr * 36 + k0]);
                bF[ni][1] = __float_as_uint(Bs[nr * 36 + k0 + 4]);
            }
#pragma unroll
            for (int mi = 0; mi < 4; mi++)
#pragma unroll
                for (int ni = 0; ni < 4; ni++) mma8(acc[mi][ni], aF[mi], bF[ni]);
        }
        __syncthreads();
    }

    // epilogue
    float* outC = out + OUT_C;
#pragma unroll
    for (int mi = 0; mi < 4; mi++) {
#pragma unroll
        for (int ni = 0; ni < 4; ni++) {
            int row0 = bi * 128 + wm * 64 + mi * 16 + (lane >> 2);
            int col  = bj * 128 + wn * 32 + ni * 8 + (lane & 3) * 2;
#pragma unroll
            for (int h = 0; h < 2; h++) {
                int rr = row0 + h * 8;
                float d0 = acc[mi][ni][2 * h], d1 = acc[mi][ni][2 * h + 1];
                float sn = g_sn[rr];
                float c0 = sqrtf(fmaxf(sn + g_tn[col]     - 2.f * d0, 0.f));
                float c1 = sqrtf(fmaxf(sn + g_tn[col + 1] - 2.f * d1, 0.f));
                outC[(size_t)rr * N + col]     = c0;
                outC[(size_t)rr * N + col + 1] = c1;
                __nv_bfloat162 kk = __floats2bfloat162_rn(__expf(-0.125f * c0),
                                                          __expf(-0.125f * c1));
                *(__nv_bfloat162*)&g_Kb[(size_t)rr * N + col] = kk;
            }
        }
    }
}

// ---- u = a / (K v + stab) : one warp per row ----
__global__ void row_kernel() {
    __shared__ float vs[N];
    int tid = threadIdx.x;
#pragma unroll
    for (int q = 0; q < 4; q++) {
        int f = tid + 256 * q;
        ((float4*)vs)[f] = ((const float4*)g_v)[f];
    }
    __syncthreads();
    int lane = tid & 31;
    int row = blockIdx.x * 8 + (tid >> 5);
    const __nv_bfloat16* Kr = g_Kb + (size_t)row * N;
    float s = 0.f;
#pragma unroll 8
    for (int c = 0; c < 32; c++) {
        int j = c * 128 + lane * 4;
        uint2 dr = *(const uint2*)(Kr + j);
        float2 f01 = __bfloat1622float2(*reinterpret_cast<__nv_bfloat162*>(&dr.x));
        float2 f23 = __bfloat1622float2(*reinterpret_cast<__nv_bfloat162*>(&dr.y));
        float4 vv = *(const float4*)(vs + j);
        s += f01.x * vv.x + f01.y * vv.y + f23.x * vv.z + f23.y * vv.w;
    }
#pragma unroll
    for (int o = 16; o > 0; o >>= 1) s += __shfl_xor_sync(0xffffffffu, s, o);
    if (lane == 0) g_u[row] = (1.0f / N) / (s + 1e-8f);
}

// ---- partial column sums z_b[j] = sum_{i in block rows} K[i][j] u[i] (deterministic) ----
__global__ void col_kernel() {
    __shared__ float us[32];
    int tid = threadIdx.x;
    int i0 = blockIdx.x * 32;
    if (tid < 32) us[tid] = g_u[i0 + tid];
    __syncthreads();
    float acc[16];
#pragma unroll
    for (int e = 0; e < 16; e++) acc[e] = 0.f;
    for (int i = 0; i < 32; i++) {
        float u = us[i];
        const __nv_bfloat16* Kr = g_Kb + (size_t)(i0 + i) * N;
#pragma unroll
        for (int s = 0; s < 4; s++) {
            int j = s * 1024 + tid * 4;
            uint2 dr = *(const uint2*)(Kr + j);
            float2 f01 = __bfloat1622float2(*reinterpret_cast<__nv_bfloat162*>(&dr.x));
            float2 f23 = __bfloat1622float2(*reinterpret_cast<__nv_bfloat162*>(&dr.y));
            acc[s * 4 + 0] += f01.x * u;
            acc[s * 4 + 1] += f01.y * u;
            acc[s * 4 + 2] += f23.x * u;
            acc[s * 4 + 3] += f23.y * u;
        }
    }
    float* zp = g_zp + (size_t)blockIdx.x * N;
#pragma unroll
    for (int s = 0; s < 4; s++) {
        float4 v4 = make_float4(acc[s * 4 + 0], acc[s * 4 + 1], acc[s * 4 + 2], acc[s * 4 + 3]);
        *(float4*)&zp[s * 1024 + tid * 4] = v4;
    }
}

// ---- v = b / (sum_b z_b + stab) ----
__global__ void fin_kernel() {
    int j = blockIdx.x * 256 + threadIdx.x;
    float s = 0.f;
#pragma unroll 8
    for (int k = 0; k < 128; k++) s += g_zp[(size_t)k * N + j];
    g_v[j] = (1.0f / N) / (s + 1e-8f);
}

// ---- coupling = u * exp(-C/8) * v ; per-row loss partials ----
__global__ void final_kernel(float* __restrict__ out) {
    int row = blockIdx.x, tid = threadIdx.x;
    float u = g_u[row];
    const float* Crow = out + OUT_C + (size_t)row * N;
    float* Prow = out + OUT_P + (size_t)row * N;
    float ls = 0.f;
#pragma unroll 4
    for (int s = 0; s < 16; s++) {
        int j = s * 256 + tid;
        float C = Crow[j];
        float cp = u * __expf(-0.125f * C) * g_v[j];
        Prow[j] = cp;
        ls += cp * C;
    }
    __shared__ float red[256];
    red[tid] = ls;
    __syncthreads();
    for (int o = 128; o > 0; o >>= 1) {
        if (tid < o) red[tid] += red[tid + o];
        __syncthreads();
    }
    if (tid == 0) g_part[row] = red[0];
}

__global__ void loss_kernel(float* __restrict__ out) {
    int tid = threadIdx.x;
    float s = 0.f;
#pragma unroll
    for (int q = 0; q < 16; q++) s += g_part[tid + q * 256];
    __shared__ float red[256];
    red[tid] = s;
    __syncthreads();
    for (int o = 128; o > 0; o >>= 1) {
        if (tid < o) red[tid] += red[tid + o];
        __syncthreads();
    }
    if (tid == 0) out[0] = red[0] * (1.0f / ((float)N * (float)N));
}

extern "C" void kernel_launch(void* const* d_in, const int* in_sizes, int n_in,
                              void* d_out, int out_size) {
    const float* S  = (const float*)d_in[0];
    const float* Tm = (const float*)d_in[1];
    float* out = (float*)d_out;

    init_kernel<<<16, 256>>>();
    norms_kernel<<<1024, 256>>>(S, Tm);
    gemm_kernel<<<dim3(32, 32), 256>>>(S, Tm, out);
    for (int it = 0; it < 10; it++) {
        row_kernel<<<512, 256>>>();
        col_kernel<<<128, 256>>>();
        fin_kernel<<<16, 256>>>();
    }
    final_kernel<<<4096, 256>>>(out);
    loss_kernel<<<1, 256>>>(out);
}

// round 4
// speedup vs baseline: 1.0588x; 1.0588x over previous
#include <cuda_runtime.h>
#include <cuda_bf16.h>
#include <cstdint>

#define N 4096
#define D 512
#define NN ((size_t)N * (size_t)N)
#define OUT_P 1
#define OUT_C (1 + 16777216)

// ---- device scratch (no allocations allowed) ----
__device__ __align__(16) __nv_bfloat16 g_Kb[NN]; // 32 MB bf16 Gibbs kernel (L2-pinned)
__device__ __align__(16) float g_zp[128 * N];    // deterministic column-sum partials (2 MB)
__device__ __align__(16) float g_sn[N], g_tn[N]; // row norms of S and T
__device__ __align__(16) float g_u[N], g_v[N];   // Sinkhorn scalings
__device__ __align__(16) float g_part[N];        // per-row loss partials

// ---- L2 evict_last via cache-hint policy (legal at any access width) ----
__device__ __forceinline__ uint64_t evict_last_policy() {
    uint64_t pol;
    asm("createpolicy.fractional.L2::evict_last.b64 %0, 1.0;" : "=l"(pol));
    return pol;
}
__device__ __forceinline__ uint4 ldK16(const __nv_bfloat16* p, uint64_t pol) {
    uint4 r;
    asm volatile("ld.global.nc.L2::cache_hint.v4.u32 {%0,%1,%2,%3}, [%4], %5;"
                 : "=r"(r.x), "=r"(r.y), "=r"(r.z), "=r"(r.w)
                 : "l"(p), "l"(pol));
    return r;
}
__device__ __forceinline__ void stK4(__nv_bfloat16* p, uint32_t v, uint64_t pol) {
    asm volatile("st.global.L2::cache_hint.u32 [%0], %1, %2;"
                 :: "l"(p), "r"(v), "l"(pol));
}

__device__ __forceinline__ void mma8(float* c, const uint32_t* a, const uint32_t* b) {
    asm volatile(
        "mma.sync.aligned.m16n8k8.row.col.f32.tf32.tf32.f32 "
        "{%0,%1,%2,%3},{%4,%5,%6,%7},{%8,%9},{%0,%1,%2,%3};"
        : "+f"(c[0]), "+f"(c[1]), "+f"(c[2]), "+f"(c[3])
        : "r"(a[0]), "r"(a[1]), "r"(a[2]), "r"(a[3]), "r"(b[0]), "r"(b[1]));
}

// ---- init: v0 = 1 ----
__global__ void init_kernel() {
    int i = blockIdx.x * blockDim.x + threadIdx.x;
    if (i < N) g_v[i] = 1.0f;
}

// ---- row norms: one warp per row (S then T) ----
__global__ void norms_kernel(const float* __restrict__ S, const float* __restrict__ Tm) {
    int w = blockIdx.x * 8 + (threadIdx.x >> 5);
    int lane = threadIdx.x & 31;
    const float* src = (w < N) ? (S + (size_t)w * D) : (Tm + (size_t)(w - N) * D);
    float s = 0.f;
#pragma unroll
    for (int c = 0; c < 4; c++) {
        float4 a = *(const float4*)(src + c * 128 + lane * 4);
        s += a.x * a.x + a.y * a.y + a.z * a.z + a.w * a.w;
    }
#pragma unroll
    for (int o = 16; o > 0; o >>= 1) s += __shfl_xor_sync(0xffffffffu, s, o);
    if (lane == 0) {
        if (w < N) g_sn[w] = s;
        else       g_tn[w - N] = s;
    }
}

// ---- TF32 tensor-core GEMM, cp.async double-buffered, k-chunk 16 ----
// 128x128 block tile, 8 warps (2x4), warp tile 64x32.
// C written streaming (.cs scalar); K written evict_last.
__global__ void __launch_bounds__(256) gemm_kernel(const float* __restrict__ S,
                                                   const float* __restrict__ Tm,
                                                   float* __restrict__ out) {
    __shared__ float As[2][128 * 20];   // 16 floats/row + pad 4 (80B rows, 16B-aligned)
    __shared__ float Bs[2][128 * 20];
    const int tid  = threadIdx.x;
    const int lane = tid & 31, warp = tid >> 5;
    const int wm = warp & 1, wn = warp >> 1;
    const int bi = blockIdx.y, bj = blockIdx.x;

    float acc[4][4][4];
#pragma unroll
    for (int a = 0; a < 4; a++)
#pragma unroll
        for (int b = 0; b < 4; b++)
#pragma unroll
            for (int r = 0; r < 4; r++) acc[a][b][r] = 0.f;

    const float* Sb = S  + (size_t)bi * 128 * D;
    const float* Tb = Tm + (size_t)bj * 128 * D;

    auto load_chunk = [&](int kc, int buf) {
#pragma unroll
        for (int q = 0; q < 2; q++) {
            int f = tid + 256 * q;
            int r = f >> 2, kg = f & 3;
            const float* sa = Sb + (size_t)r * D + kc + kg * 4;
            const float* sb = Tb + (size_t)r * D + kc + kg * 4;
            uint32_t da = (uint32_t)__cvta_generic_to_shared(&As[buf][r * 20 + kg * 4]);
            uint32_t db = (uint32_t)__cvta_generic_to_shared(&Bs[buf][r * 20 + kg * 4]);
            asm volatile("cp.async.cg.shared.global [%0], [%1], 16;\n\t"
                         "cp.async.cg.shared.global [%2], [%3], 16;"
                         :: "r"(da), "l"(sa), "r"(db), "l"(sb));
        }
        asm volatile("cp.async.commit_group;");
    };

    load_chunk(0, 0);
    for (int c = 0; c < 32; c++) {
        if (c + 1 < 32) {
            load_chunk((c + 1) * 16, (c + 1) & 1);
            asm volatile("cp.async.wait_group 1;");
        } else {
            asm volatile("cp.async.wait_group 0;");
        }
        __syncthreads();
        const float* Ab = As[c & 1];
        const float* Bb = Bs[c & 1];
#pragma unroll
        for (int k8 = 0; k8 < 2; k8++) {
            int k0 = k8 * 8 + (lane & 3);
            uint32_t aF[4][4], bF[4][2];
#pragma unroll
            for (int mi = 0; mi < 4; mi++) {
                int row = wm * 64 + mi * 16 + (lane >> 2);
                aF[mi][0] = __float_as_uint(Ab[row * 20 + k0]);
                aF[mi][1] = __float_as_uint(Ab[(row + 8) * 20 + k0]);
                aF[mi][2] = __float_as_uint(Ab[row * 20 + k0 + 4]);
                aF[mi][3] = __float_as_uint(Ab[(row + 8) * 20 + k0 + 4]);
            }
#pragma unroll
            for (int ni = 0; ni < 4; ni++) {
                int nr = wn * 32 + ni * 8 + (lane >> 2);
                bF[ni][0] = __float_as_uint(Bb[nr * 20 + k0]);
                bF[ni][1] = __float_as_uint(Bb[nr * 20 + k0 + 4]);
            }
#pragma unroll
            for (int mi = 0; mi < 4; mi++)
#pragma unroll
                for (int ni = 0; ni < 4; ni++) mma8(acc[mi][ni], aF[mi], bF[ni]);
        }
        __syncthreads();
    }

    // epilogue: C = sqrt(max(sn+tn-2*dot,0)) streamed out; K = exp(-C/8) pinned in L2
    uint64_t pol = evict_last_policy();
    float* outC = out + OUT_C;
#pragma unroll
    for (int mi = 0; mi < 4; mi++) {
#pragma unroll
        for (int ni = 0; ni < 4; ni++) {
            int row0 = bi * 128 + wm * 64 + mi * 16 + (lane >> 2);
            int col  = bj * 128 + wn * 32 + ni * 8 + (lane & 3) * 2;
#pragma unroll
            for (int h = 0; h < 2; h++) {
                int rr = row0 + h * 8;
                float d0 = acc[mi][ni][2 * h], d1 = acc[mi][ni][2 * h + 1];
                float sn = g_sn[rr];
                float c0 = sqrtf(fmaxf(sn + g_tn[col]     - 2.f * d0, 0.f));
                float c1 = sqrtf(fmaxf(sn + g_tn[col + 1] - 2.f * d1, 0.f));
                __stcs(&outC[(size_t)rr * N + col],     c0);
                __stcs(&outC[(size_t)rr * N + col + 1], c1);
                __nv_bfloat162 kk = __floats2bfloat162_rn(__expf(-0.125f * c0),
                                                          __expf(-0.125f * c1));
                stK4(&g_Kb[(size_t)rr * N + col], *(uint32_t*)&kk, pol);
            }
        }
    }
}

// ---- u = a / (K v + stab) : one warp per row, 16B K loads ----
__global__ void row_kernel() {
    __shared__ float vs[N];
    int tid = threadIdx.x;
#pragma unroll
    for (int q = 0; q < 4; q++) {
        int f = tid + 256 * q;
        ((float4*)vs)[f] = ((const float4*)g_v)[f];
    }
    __syncthreads();
    uint64_t pol = evict_last_policy();
    int lane = tid & 31;
    int row = blockIdx.x * 8 + (tid >> 5);
    const __nv_bfloat16* Kr = g_Kb + (size_t)row * N;
    float s = 0.f;
#pragma unroll
    for (int c = 0; c < 16; c++) {
        int j = c * 256 + lane * 8;
        uint4 dr = ldK16(Kr + j, pol);
        float2 f0 = __bfloat1622float2(*reinterpret_cast<__nv_bfloat162*>(&dr.x));
        float2 f1 = __bfloat1622float2(*reinterpret_cast<__nv_bfloat162*>(&dr.y));
        float2 f2 = __bfloat1622float2(*reinterpret_cast<__nv_bfloat162*>(&dr.z));
        float2 f3 = __bfloat1622float2(*reinterpret_cast<__nv_bfloat162*>(&dr.w));
        float4 va = *(const float4*)(vs + j);
        float4 vb = *(const float4*)(vs + j + 4);
        s += f0.x * va.x + f0.y * va.y + f1.x * va.z + f1.y * va.w;
        s += f2.x * vb.x + f2.y * vb.y + f3.x * vb.z + f3.y * vb.w;
    }
#pragma unroll
    for (int o = 16; o > 0; o >>= 1) s += __shfl_xor_sync(0xffffffffu, s, o);
    if (lane == 0) g_u[row] = (1.0f / N) / (s + 1e-8f);
}

// ---- partial column sums z_b[j] = sum_{i in 32 block rows} K[i][j] u[i] ----
// 512 threads; thread owns 8 contiguous columns (one 16B load per row).
__global__ void __launch_bounds__(512) col_kernel() {
    __shared__ float us[32];
    int tid = threadIdx.x;
    int i0 = blockIdx.x * 32;
    if (tid < 32) us[tid] = g_u[i0 + tid];
    __syncthreads();
    uint64_t pol = evict_last_policy();
    float acc[8];
#pragma unroll
    for (int e = 0; e < 8; e++) acc[e] = 0.f;
    const __nv_bfloat16* Kp = g_Kb + (size_t)i0 * N + tid * 8;
    for (int i = 0; i < 32; i++) {
        float u = us[i];
        uint4 dr = ldK16(Kp + (size_t)i * N, pol);
        float2 f0 = __bfloat1622float2(*reinterpret_cast<__nv_bfloat162*>(&dr.x));
        float2 f1 = __bfloat1622float2(*reinterpret_cast<__nv_bfloat162*>(&dr.y));
        float2 f2 = __bfloat1622float2(*reinterpret_cast<__nv_bfloat162*>(&dr.z));
        float2 f3 = __bfloat1622float2(*reinterpret_cast<__nv_bfloat162*>(&dr.w));
        acc[0] += f0.x * u; acc[1] += f0.y * u;
        acc[2] += f1.x * u; acc[3] += f1.y * u;
        acc[4] += f2.x * u; acc[5] += f2.y * u;
        acc[6] += f3.x * u; acc[7] += f3.y * u;
    }
    float* zp = g_zp + (size_t)blockIdx.x * N + tid * 8;
    *(float4*)zp       = make_float4(acc[0], acc[1], acc[2], acc[3]);
    *(float4*)(zp + 4) = make_float4(acc[4], acc[5], acc[6], acc[7]);
}

// ---- v = b / (sum_b z_b + stab) ----
__global__ void fin_kernel() {
    int j = blockIdx.x * 256 + threadIdx.x;
    float s = 0.f;
#pragma unroll 8
    for (int k = 0; k < 128; k++) s += g_zp[(size_t)k * N + j];
    g_v[j] = (1.0f / N) / (s + 1e-8f);
}

// ---- coupling = u * exp(-C/8) * v ; per-row loss partials ----
// NOTE: out+1 offsets are only 4B-aligned -> scalar accesses only.
__global__ void final_kernel(float* __restrict__ out) {
    int row = blockIdx.x, tid = threadIdx.x;
    float u = g_u[row];
    const float* Crow = out + OUT_C + (size_t)row * N;
    float* Prow = out + OUT_P + (size_t)row * N;
    float ls = 0.f;
#pragma unroll 4
    for (int s = 0; s < 16; s++) {
        int j = s * 256 + tid;
        float C = __ldcs(Crow + j);
        float cp = u * __expf(-0.125f * C) * g_v[j];
        __stcs(Prow + j, cp);
        ls += cp * C;
    }
    __shared__ float red[256];
    red[tid] = ls;
    __syncthreads();
    for (int o = 128; o > 0; o >>= 1) {
        if (tid < o) red[tid] += red[tid + o];
        __syncthreads();
    }
    if (tid == 0) g_part[row] = red[0];
}

__global__ void loss_kernel(float* __restrict__ out) {
    int tid = threadIdx.x;
    float s = 0.f;
#pragma unroll
    for (int q = 0; q < 16; q++) s += g_part[tid + q * 256];
    __shared__ float red[256];
    red[tid] = s;
    __syncthreads();
    for (int o = 128; o > 0; o >>= 1) {
        if (tid < o) red[tid] += red[tid + o];
        __syncthreads();
    }
    if (tid == 0) out[0] = red[0] * (1.0f / ((float)N * (float)N));
}

extern "C" void kernel_launch(void* const* d_in, const int* in_sizes, int n_in,
                              void* d_out, int out_size) {
    const float* S  = (const float*)d_in[0];
    const float* Tm = (const float*)d_in[1];
    float* out = (float*)d_out;

    init_kernel<<<16, 256>>>();
    norms_kernel<<<1024, 256>>>(S, Tm);
    gemm_kernel<<<dim3(32, 32), 256>>>(S, Tm, out);
    for (int it = 0; it < 10; it++) {
        row_kernel<<<512, 256>>>();
        col_kernel<<<128, 512>>>();
        fin_kernel<<<16, 256>>>();
    }
    final_kernel<<<4096, 256>>>(out);
    loss_kernel<<<1, 256>>>(out);
}

// round 5
// speedup vs baseline: 1.2196x; 1.1519x over previous
#include <cuda_runtime.h>
#include <cuda_bf16.h>
#include <cstdint>

#define N 4096
#define D 512
#define NN ((size_t)N * (size_t)N)
#define OUT_P 1
#define OUT_C (1 + 16777216)

// ---- device scratch (no allocations allowed) ----
__device__ __align__(16) __nv_bfloat16 g_Kb[NN]; // 32 MB bf16 Gibbs kernel
__device__ __align__(16) __nv_bfloat16 g_Sb[(size_t)N * D]; // bf16 copy of S (4 MB)
__device__ __align__(16) __nv_bfloat16 g_Tb[(size_t)N * D]; // bf16 copy of T (4 MB)
__device__ __align__(16) float g_zp[128 * N];    // deterministic column-sum partials (2 MB)
__device__ __align__(16) float g_sn[N], g_tn[N]; // row norms of S and T (fp32, exact)
__device__ __align__(16) float g_u[N], g_v[N];   // Sinkhorn scalings
__device__ __align__(16) float g_part[N];        // per-row loss partials

// ---- L2 evict_last via cache-hint policy ----
__device__ __forceinline__ uint64_t evict_last_policy() {
    uint64_t pol;
    asm("createpolicy.fractional.L2::evict_last.b64 %0, 1.0;" : "=l"(pol));
    return pol;
}
__device__ __forceinline__ uint4 ldK16(const __nv_bfloat16* p, uint64_t pol) {
    uint4 r;
    asm volatile("ld.global.nc.L2::cache_hint.v4.u32 {%0,%1,%2,%3}, [%4], %5;"
                 : "=r"(r.x), "=r"(r.y), "=r"(r.z), "=r"(r.w)
                 : "l"(p), "l"(pol));
    return r;
}
__device__ __forceinline__ void stK4(__nv_bfloat16* p, uint32_t v, uint64_t pol) {
    asm volatile("st.global.L2::cache_hint.u32 [%0], %1, %2;"
                 :: "l"(p), "r"(v), "l"(pol));
}

// bf16 m16n8k16 mma, fp32 accumulate
__device__ __forceinline__ void mma16(float* c, const uint32_t* a, const uint32_t* b) {
    asm volatile(
        "mma.sync.aligned.m16n8k16.row.col.f32.bf16.bf16.f32 "
        "{%0,%1,%2,%3},{%4,%5,%6,%7},{%8,%9},{%0,%1,%2,%3};"
        : "+f"(c[0]), "+f"(c[1]), "+f"(c[2]), "+f"(c[3])
        : "r"(a[0]), "r"(a[1]), "r"(a[2]), "r"(a[3]), "r"(b[0]), "r"(b[1]));
}

// ---- init: v0 = 1 ----
__global__ void init_kernel() {
    int i = blockIdx.x * blockDim.x + threadIdx.x;
    if (i < N) g_v[i] = 1.0f;
}

// ---- convert fp32 -> bf16 (S and T) ----
__global__ void cvt_kernel(const float* __restrict__ X, __nv_bfloat16* __restrict__ Y) {
    size_t i = ((size_t)blockIdx.x * blockDim.x + threadIdx.x) * 4;
    float4 a = *(const float4*)(X + i);
    uint2 o;
    __nv_bfloat162 lo = __floats2bfloat162_rn(a.x, a.y);
    __nv_bfloat162 hi = __floats2bfloat162_rn(a.z, a.w);
    o.x = *(uint32_t*)&lo;
    o.y = *(uint32_t*)&hi;
    *(uint2*)(Y + i) = o;
}

// ---- row norms in fp32 from the original inputs: one warp per row ----
__global__ void norms_kernel(const float* __restrict__ S, const float* __restrict__ Tm) {
    int w = blockIdx.x * 8 + (threadIdx.x >> 5);
    int lane = threadIdx.x & 31;
    const float* src = (w < N) ? (S + (size_t)w * D) : (Tm + (size_t)(w - N) * D);
    float s = 0.f;
#pragma unroll
    for (int c = 0; c < 4; c++) {
        float4 a = *(const float4*)(src + c * 128 + lane * 4);
        s += a.x * a.x + a.y * a.y + a.z * a.z + a.w * a.w;
    }
#pragma unroll
    for (int o = 16; o > 0; o >>= 1) s += __shfl_xor_sync(0xffffffffu, s, o);
    if (lane == 0) {
        if (w < N) g_sn[w] = s;
        else       g_tn[w - N] = s;
    }
}

// ---- bf16 tensor-core GEMM, cp.async double-buffered, k-chunk 32 ----
// 128x128 block tile, 8 warps (2x4), warp tile 64x32, mma.m16n8k16.
// SMEM row stride 80B (64B data + 16B pad): conflict-free fragment LDS.
__global__ void __launch_bounds__(256) gemm_kernel(float* __restrict__ out) {
    __shared__ __align__(16) char As[2][128 * 80];
    __shared__ __align__(16) char Bs[2][128 * 80];
    const int tid  = threadIdx.x;
    const int lane = tid & 31, warp = tid >> 5;
    const int wm = warp & 1, wn = warp >> 1;
    const int quad = lane >> 2, tb = (lane & 3) * 4;   // fragment byte offset within k16
    const int bi = blockIdx.y, bj = blockIdx.x;

    float acc[4][4][4];
#pragma unroll
    for (int a = 0; a < 4; a++)
#pragma unroll
        for (int b = 0; b < 4; b++)
#pragma unroll
            for (int r = 0; r < 4; r++) acc[a][b][r] = 0.f;

    const __nv_bfloat16* Sb = g_Sb + (size_t)bi * 128 * D;
    const __nv_bfloat16* Tb = g_Tb + (size_t)bj * 128 * D;

    // one 32-wide k-chunk (64B/row) of A and B into buffer `buf`
    auto load_chunk = [&](int kc, int buf) {
#pragma unroll
        for (int q = 0; q < 2; q++) {
            int f = tid + 256 * q;            // 0..511
            int r = f >> 2, seg = f & 3;      // row, 16B segment
            const __nv_bfloat16* sa = Sb + (size_t)r * D + kc + seg * 8;
            const __nv_bfloat16* sb = Tb + (size_t)r * D + kc + seg * 8;
            uint32_t da = (uint32_t)__cvta_generic_to_shared(&As[buf][r * 80 + seg * 16]);
            uint32_t db = (uint32_t)__cvta_generic_to_shared(&Bs[buf][r * 80 + seg * 16]);
            asm volatile("cp.async.cg.shared.global [%0], [%1], 16;\n\t"
                         "cp.async.cg.shared.global [%2], [%3], 16;"
                         :: "r"(da), "l"(sa), "r"(db), "l"(sb));
        }
        asm volatile("cp.async.commit_group;");
    };

    load_chunk(0, 0);
    for (int c = 0; c < 16; c++) {
        if (c + 1 < 16) {
            load_chunk((c + 1) * 32, (c + 1) & 1);
            asm volatile("cp.async.wait_group 1;");
        } else {
            asm volatile("cp.async.wait_group 0;");
        }
        __syncthreads();
        const char* Ab = As[c & 1];
        const char* Bb = Bs[c & 1];
#pragma unroll
        for (int s = 0; s < 2; s++) {         // two k16 steps per chunk
            const int kb = s * 32 + tb;       // byte offset of this thread's k pair
            uint32_t aF[4][4], bF[4][2];
#pragma unroll
            for (int mi = 0; mi < 4; mi++) {
                int row = wm * 64 + mi * 16 + quad;
                aF[mi][0] = *(const uint32_t*)(Ab + row * 80 + kb);
                aF[mi][1] = *(const uint32_t*)(Ab + (row + 8) * 80 + kb);
                aF[mi][2] = *(const uint32_t*)(Ab + row * 80 + kb + 16);
                aF[mi][3] = *(const uint32_t*)(Ab + (row + 8) * 80 + kb + 16);
            }
#pragma unroll
            for (int ni = 0; ni < 4; ni++) {
                int nr = wn * 32 + ni * 8 + quad;
                bF[ni][0] = *(const uint32_t*)(Bb + nr * 80 + kb);
                bF[ni][1] = *(const uint32_t*)(Bb + nr * 80 + kb + 16);
            }
#pragma unroll
            for (int mi = 0; mi < 4; mi++)
#pragma unroll
                for (int ni = 0; ni < 4; ni++) mma16(acc[mi][ni], aF[mi], bF[ni]);
        }
        __syncthreads();
    }

    // epilogue: C = sqrt(max(sn+tn-2*dot,0)) streamed; K = exp(-C/8) evict_last
    uint64_t pol = evict_last_policy();
    float* outC = out + OUT_C;
#pragma unroll
    for (int mi = 0; mi < 4; mi++) {
#pragma unroll
        for (int ni = 0; ni < 4; ni++) {
            int row0 = bi * 128 + wm * 64 + mi * 16 + quad;
            int col  = bj * 128 + wn * 32 + ni * 8 + (lane & 3) * 2;
#pragma unroll
            for (int h = 0; h < 2; h++) {
                int rr = row0 + h * 8;
                float d0 = acc[mi][ni][2 * h], d1 = acc[mi][ni][2 * h + 1];
                float sn = g_sn[rr];
                float c0 = sqrtf(fmaxf(sn + g_tn[col]     - 2.f * d0, 0.f));
                float c1 = sqrtf(fmaxf(sn + g_tn[col + 1] - 2.f * d1, 0.f));
                __stcs(&outC[(size_t)rr * N + col],     c0);
                __stcs(&outC[(size_t)rr * N + col + 1], c1);
                __nv_bfloat162 kk = __floats2bfloat162_rn(__expf(-0.125f * c0),
                                                          __expf(-0.125f * c1));
                stK4(&g_Kb[(size_t)rr * N + col], *(uint32_t*)&kk, pol);
            }
        }
    }
}

// ---- u = a / (K v + stab) : one warp per row, 16B K loads ----
__global__ void row_kernel() {
    __shared__ float vs[N];
    int tid = threadIdx.x;
#pragma unroll
    for (int q = 0; q < 4; q++) {
        int f = tid + 256 * q;
        ((float4*)vs)[f] = ((const float4*)g_v)[f];
    }
    __syncthreads();
    uint64_t pol = evict_last_policy();
    int lane = tid & 31;
    int row = blockIdx.x * 8 + (tid >> 5);
    const __nv_bfloat16* Kr = g_Kb + (size_t)row * N;
    float s = 0.f;
#pragma unroll
    for (int c = 0; c < 16; c++) {
        int j = c * 256 + lane * 8;
        uint4 dr = ldK16(Kr + j, pol);
        float2 f0 = __bfloat1622float2(*reinterpret_cast<__nv_bfloat162*>(&dr.x));
        float2 f1 = __bfloat1622float2(*reinterpret_cast<__nv_bfloat162*>(&dr.y));
        float2 f2 = __bfloat1622float2(*reinterpret_cast<__nv_bfloat162*>(&dr.z));
        float2 f3 = __bfloat1622float2(*reinterpret_cast<__nv_bfloat162*>(&dr.w));
        float4 va = *(const float4*)(vs + j);
        float4 vb = *(const float4*)(vs + j + 4);
        s += f0.x * va.x + f0.y * va.y + f1.x * va.z + f1.y * va.w;
        s += f2.x * vb.x + f2.y * vb.y + f3.x * vb.z + f3.y * vb.w;
    }
#pragma unroll
    for (int o = 16; o > 0; o >>= 1) s += __shfl_xor_sync(0xffffffffu, s, o);
    if (lane == 0) g_u[row] = (1.0f / N) / (s + 1e-8f);
}

// ---- partial column sums z_b[j] = sum_{i in 32 block rows} K[i][j] u[i] ----
__global__ void __launch_bounds__(512) col_kernel() {
    __shared__ float us[32];
    int tid = threadIdx.x;
    int i0 = blockIdx.x * 32;
    if (tid < 32) us[tid] = g_u[i0 + tid];
    __syncthreads();
    uint64_t pol = evict_last_policy();
    float acc[8];
#pragma unroll
    for (int e = 0; e < 8; e++) acc[e] = 0.f;
    const __nv_bfloat16* Kp = g_Kb + (size_t)i0 * N + tid * 8;
    for (int i = 0; i < 32; i++) {
        float u = us[i];
        uint4 dr = ldK16(Kp + (size_t)i * N, pol);
        float2 f0 = __bfloat1622float2(*reinterpret_cast<__nv_bfloat162*>(&dr.x));
        float2 f1 = __bfloat1622float2(*reinterpret_cast<__nv_bfloat162*>(&dr.y));
        float2 f2 = __bfloat1622float2(*reinterpret_cast<__nv_bfloat162*>(&dr.z));
        float2 f3 = __bfloat1622float2(*reinterpret_cast<__nv_bfloat162*>(&dr.w));
        acc[0] += f0.x * u; acc[1] += f0.y * u;
        acc[2] += f1.x * u; acc[3] += f1.y * u;
        acc[4] += f2.x * u; acc[5] += f2.y * u;
        acc[6] += f3.x * u; acc[7] += f3.y * u;
    }
    float* zp = g_zp + (size_t)blockIdx.x * N + tid * 8;
    *(float4*)zp       = make_float4(acc[0], acc[1], acc[2], acc[3]);
    *(float4*)(zp + 4) = make_float4(acc[4], acc[5], acc[6], acc[7]);
}

// ---- v = b / (sum_b z_b + stab) ----
__global__ void fin_kernel() {
    int j = blockIdx.x * 256 + threadIdx.x;
    float s = 0.f;
#pragma unroll 8
    for (int k = 0; k < 128; k++) s += g_zp[(size_t)k * N + j];
    g_v[j] = (1.0f / N) / (s + 1e-8f);
}

// ---- coupling = u * exp(-C/8) * v ; per-row loss partials ----
// out+1 offsets are only 4B-aligned -> scalar accesses.
__global__ void final_kernel(float* __restrict__ out) {
    int row = blockIdx.x, tid = threadIdx.x;
    float u = g_u[row];
    const float* Crow = out + OUT_C + (size_t)row * N;
    float* Prow = out + OUT_P + (size_t)row * N;
    float ls = 0.f;
#pragma unroll 4
    for (int s = 0; s < 16; s++) {
        int j = s * 256 + tid;
        float C = __ldcs(Crow + j);
        float cp = u * __expf(-0.125f * C) * g_v[j];
        __stcs(Prow + j, cp);
        ls += cp * C;
    }
    __shared__ float red[256];
    red[tid] = ls;
    __syncthreads();
    for (int o = 128; o > 0; o >>= 1) {
        if (tid < o) red[tid] += red[tid + o];
        __syncthreads();
    }
    if (tid == 0) g_part[row] = red[0];
}

__global__ void loss_kernel(float* __restrict__ out) {
    int tid = threadIdx.x;
    float s = 0.f;
#pragma unroll
    for (int q = 0; q < 16; q++) s += g_part[tid + q * 256];
    __shared__ float red[256];
    red[tid] = s;
    __syncthreads();
    for (int o = 128; o > 0; o >>= 1) {
        if (tid < o) red[tid] += red[tid + o];
        __syncthreads();
    }
    if (tid == 0) out[0] = red[0] * (1.0f / ((float)N * (float)N));
}

extern "C" void kernel_launch(void* const* d_in, const int* in_sizes, int n_in,
                              void* d_out, int out_size) {
    const float* S  = (const float*)d_in[0];
    const float* Tm = (const float*)d_in[1];
    float* out = (float*)d_out;

    __nv_bfloat16 *dSb, *dTb;
    cudaGetSymbolAddress((void**)&dSb, g_Sb);
    cudaGetSymbolAddress((void**)&dTb, g_Tb);

    init_kernel<<<16, 256>>>();
    cvt_kernel<<<2048, 256>>>(S, dSb);
    cvt_kernel<<<2048, 256>>>(Tm, dTb);
    norms_kernel<<<1024, 256>>>(S, Tm);
    gemm_kernel<<<dim3(32, 32), 256>>>(out);
    for (int it = 0; it < 10; it++) {
        row_kernel<<<512, 256>>>();
        col_kernel<<<128, 512>>>();
        fin_kernel<<<16, 256>>>();
    }
    final_kernel<<<4096, 256>>>(out);
    loss_kernel<<<1, 256>>>(out);
}

// round 7
// speedup vs baseline: 1.2292x; 1.0079x over previous
#include <cuda_runtime.h>
#include <cuda_bf16.h>
#include <cstdint>

#define N 4096
#define D 512
#define NN ((size_t)N * (size_t)N)
#define OUT_P 1
#define OUT_C (1 + 16777216)

// ---- device scratch (no allocations allowed) ----
__device__ __align__(16) __nv_bfloat16 g_Kb[NN]; // 32 MB bf16 Gibbs kernel
__device__ __align__(16) __nv_bfloat16 g_Sb[(size_t)N * D]; // bf16 copy of S (4 MB)
__device__ __align__(16) __nv_bfloat16 g_Tb[(size_t)N * D]; // bf16 copy of T (4 MB)
__device__ __align__(16) float g_zp[128 * N];    // deterministic column-sum partials (2 MB)
__device__ __align__(16) float g_sn[N], g_tn[N]; // row norms (fp32, exact)
__device__ __align__(16) float g_u[N], g_v[N];   // Sinkhorn scalings
__device__ __align__(16) float g_part[N];        // per-row loss partials

// ---- L2 evict_last via cache-hint policy ----
__device__ __forceinline__ uint64_t evict_last_policy() {
    uint64_t pol;
    asm("createpolicy.fractional.L2::evict_last.b64 %0, 1.0;" : "=l"(pol));
    return pol;
}
__device__ __forceinline__ uint4 ldK16(const __nv_bfloat16* p, uint64_t pol) {
    uint4 r;
    asm volatile("ld.global.nc.L2::cache_hint.v4.u32 {%0,%1,%2,%3}, [%4], %5;"
                 : "=r"(r.x), "=r"(r.y), "=r"(r.z), "=r"(r.w)
                 : "l"(p), "l"(pol));
    return r;
}
__device__ __forceinline__ uint2 ldK8(const __nv_bfloat16* p, uint64_t pol) {
    uint2 r;
    asm volatile("ld.global.nc.L2::cache_hint.v2.u32 {%0,%1}, [%2], %3;"
                 : "=r"(r.x), "=r"(r.y) : "l"(p), "l"(pol));
    return r;
}
__device__ __forceinline__ void stK4(__nv_bfloat16* p, uint32_t v, uint64_t pol) {
    asm volatile("st.global.L2::cache_hint.u32 [%0], %1, %2;"
                 :: "l"(p), "r"(v), "l"(pol));
}

// bf16 m16n8k16 mma, fp32 accumulate
__device__ __forceinline__ void mma16(float* c, const uint32_t* a, const uint32_t* b) {
    asm volatile(
        "mma.sync.aligned.m16n8k16.row.col.f32.bf16.bf16.f32 "
        "{%0,%1,%2,%3},{%4,%5,%6,%7},{%8,%9},{%0,%1,%2,%3};"
        : "+f"(c[0]), "+f"(c[1]), "+f"(c[2]), "+f"(c[3])
        : "r"(a[0]), "r"(a[1]), "r"(a[2]), "r"(a[3]), "r"(b[0]), "r"(b[1]));
}

// ---- init: v0 = 1 ----
__global__ void init_kernel() {
    int i = blockIdx.x * blockDim.x + threadIdx.x;
    if (i < N) g_v[i] = 1.0f;
}

// ---- fused convert fp32->bf16 + row sq-norms; one block = 2 rows ----
__global__ void cvt_norm_kernel(const float* __restrict__ X, __nv_bfloat16* __restrict__ Y,
                                float* __restrict__ nrm) {
    __shared__ float ws[8];
    int tid = threadIdx.x;
    size_t base = (size_t)blockIdx.x * 1024 + tid * 4;
    float4 a = *(const float4*)(X + base);
    uint2 o;
    __nv_bfloat162 lo = __floats2bfloat162_rn(a.x, a.y);
    __nv_bfloat162 hi = __floats2bfloat162_rn(a.z, a.w);
    o.x = *(uint32_t*)&lo;
    o.y = *(uint32_t*)&hi;
    *(uint2*)(Y + base) = o;
    float s = a.x * a.x + a.y * a.y + a.z * a.z + a.w * a.w;
#pragma unroll
    for (int of = 16; of > 0; of >>= 1) s += __shfl_xor_sync(0xffffffffu, s, of);
    if ((tid & 31) == 0) ws[tid >> 5] = s;
    __syncthreads();
    if (tid == 0)   nrm[blockIdx.x * 2]     = ws[0] + ws[1] + ws[2] + ws[3];
    if (tid == 128) nrm[blockIdx.x * 2 + 1] = ws[4] + ws[5] + ws[6] + ws[7];
}

// ---- bf16 tensor-core GEMM, cp.async double-buffered, k-chunk 32 ----
__global__ void __launch_bounds__(256) gemm_kernel(float* __restrict__ out) {
    __shared__ __align__(16) char As[2][128 * 80];
    __shared__ __align__(16) char Bs[2][128 * 80];
    const int tid  = threadIdx.x;
    const int lane = tid & 31, warp = tid >> 5;
    const int wm = warp & 1, wn = warp >> 1;
    const int quad = lane >> 2, tb = (lane & 3) * 4;
    const int bi = blockIdx.y, bj = blockIdx.x;

    float acc[4][4][4];
#pragma unroll
    for (int a = 0; a < 4; a++)
#pragma unroll
        for (int b = 0; b < 4; b++)
#pragma unroll
            for (int r = 0; r < 4; r++) acc[a][b][r] = 0.f;

    const __nv_bfloat16* Sb = g_Sb + (size_t)bi * 128 * D;
    const __nv_bfloat16* Tb = g_Tb + (size_t)bj * 128 * D;

    auto load_chunk = [&](int kc, int buf) {
#pragma unroll
        for (int q = 0; q < 2; q++) {
            int f = tid + 256 * q;
            int r = f >> 2, seg = f & 3;
            const __nv_bfloat16* sa = Sb + (size_t)r * D + kc + seg * 8;
            const __nv_bfloat16* sb = Tb + (size_t)r * D + kc + seg * 8;
            uint32_t da = (uint32_t)__cvta_generic_to_shared(&As[buf][r * 80 + seg * 16]);
            uint32_t db = (uint32_t)__cvta_generic_to_shared(&Bs[buf][r * 80 + seg * 16]);
            asm volatile("cp.async.cg.shared.global [%0], [%1], 16;\n\t"
                         "cp.async.cg.shared.global [%2], [%3], 16;"
                         :: "r"(da), "l"(sa), "r"(db), "l"(sb));
        }
        asm volatile("cp.async.commit_group;");
    };

    load_chunk(0, 0);
    for (int c = 0; c < 16; c++) {
        if (c + 1 < 16) {
            load_chunk((c + 1) * 32, (c + 1) & 1);
            asm volatile("cp.async.wait_group 1;");
        } else {
            asm volatile("cp.async.wait_group 0;");
        }
        __syncthreads();
        const char* Ab = As[c & 1];
        const char* Bb = Bs[c & 1];
#pragma unroll
        for (int s = 0; s < 2; s++) {
            const int kb = s * 32 + tb;
            uint32_t aF[4][4], bF[4][2];
#pragma unroll
            for (int mi = 0; mi < 4; mi++) {
                int row = wm * 64 + mi * 16 + quad;
                aF[mi][0] = *(const uint32_t*)(Ab + row * 80 + kb);
                aF[mi][1] = *(const uint32_t*)(Ab + (row + 8) * 80 + kb);
                aF[mi][2] = *(const uint32_t*)(Ab + row * 80 + kb + 16);
                aF[mi][3] = *(const uint32_t*)(Ab + (row + 8) * 80 + kb + 16);
            }
#pragma unroll
            for (int ni = 0; ni < 4; ni++) {
                int nr = wn * 32 + ni * 8 + quad;
                bF[ni][0] = *(const uint32_t*)(Bb + nr * 80 + kb);
                bF[ni][1] = *(const uint32_t*)(Bb + nr * 80 + kb + 16);
            }
#pragma unroll
            for (int mi = 0; mi < 4; mi++)
#pragma unroll
                for (int ni = 0; ni < 4; ni++) mma16(acc[mi][ni], aF[mi], bF[ni]);
        }
        __syncthreads();
    }

    uint64_t pol = evict_last_policy();
    float* outC = out + OUT_C;
#pragma unroll
    for (int mi = 0; mi < 4; mi++) {
#pragma unroll
        for (int ni = 0; ni < 4; ni++) {
            int row0 = bi * 128 + wm * 64 + mi * 16 + quad;
            int col  = bj * 128 + wn * 32 + ni * 8 + (lane & 3) * 2;
#pragma unroll
            for (int h = 0; h < 2; h++) {
                int rr = row0 + h * 8;
                float d0 = acc[mi][ni][2 * h], d1 = acc[mi][ni][2 * h + 1];
                float sn = g_sn[rr];
                float c0 = sqrtf(fmaxf(sn + g_tn[col]     - 2.f * d0, 0.f));
                float c1 = sqrtf(fmaxf(sn + g_tn[col + 1] - 2.f * d1, 0.f));
                __stcs(&outC[(size_t)rr * N + col],     c0);
                __stcs(&outC[(size_t)rr * N + col + 1], c1);
                __nv_bfloat162 kk = __floats2bfloat162_rn(__expf(-0.125f * c0),
                                                          __expf(-0.125f * c1));
                stK4(&g_Kb[(size_t)rr * N + col], *(uint32_t*)&kk, pol);
            }
        }
    }
}

// ---- u = a / (K v + stab) : HALF-row per warp, 1024 blocks x 8 warps (4 rows/blk) ----
__global__ void row_kernel() {
    __shared__ float vs[N];
    __shared__ float ps[8];
    int tid = threadIdx.x;
#pragma unroll
    for (int q = 0; q < 4; q++) {
        int f = tid + 256 * q;
        ((float4*)vs)[f] = ((const float4*)g_v)[f];
    }
    __syncthreads();
    uint64_t pol = evict_last_policy();
    int lane = tid & 31, warp = tid >> 5;
    int row  = blockIdx.x * 4 + (warp >> 1);
    int half = warp & 1;
    const __nv_bfloat16* Kr = g_Kb + (size_t)row * N + half * 2048;
    const float* vh = vs + half * 2048;
    float s = 0.f;
#pragma unroll
    for (int c = 0; c < 8; c++) {
        int j = c * 256 + lane * 8;
        uint4 dr = ldK16(Kr + j, pol);
        float2 f0 = __bfloat1622float2(*reinterpret_cast<__nv_bfloat162*>(&dr.x));
        float2 f1 = __bfloat1622float2(*reinterpret_cast<__nv_bfloat162*>(&dr.y));
        float2 f2 = __bfloat1622float2(*reinterpret_cast<__nv_bfloat162*>(&dr.z));
        float2 f3 = __bfloat1622float2(*reinterpret_cast<__nv_bfloat162*>(&dr.w));
        float4 va = *(const float4*)(vh + j);
        float4 vb = *(const float4*)(vh + j + 4);
        s += f0.x * va.x + f0.y * va.y + f1.x * va.z + f1.y * va.w;
        s += f2.x * vb.x + f2.y * vb.y + f3.x * vb.z + f3.y * vb.w;
    }
#pragma unroll
    for (int o = 16; o > 0; o >>= 1) s += __shfl_xor_sync(0xffffffffu, s, o);
    if (lane == 0) ps[warp] = s;
    __syncthreads();
    if (tid < 4)
        g_u[blockIdx.x * 4 + tid] = (1.0f / N) / (ps[2 * tid] + ps[2 * tid + 1] + 1e-8f);
}

// ---- partial column sums: 512 blocks = (32-row block) x (1024-col quarter) ----
// thread owns 4 cols (8B loads); i-loop unrolled x4 for MLP.
__global__ void __launch_bounds__(256) col_kernel() {
    __shared__ float us[32];
    int tid = threadIdx.x;
    int rb = blockIdx.x >> 2;          // 0..127 row block
    int cq = blockIdx.x & 3;           // column quarter
    int i0 = rb * 32;
    if (tid < 32) us[tid] = g_u[i0 + tid];
    __syncthreads();
    uint64_t pol = evict_last_policy();
    int col = cq * 1024 + tid * 4;
    float a0 = 0.f, a1 = 0.f, a2 = 0.f, a3 = 0.f;
    const __nv_bfloat16* Kp = g_Kb + (size_t)i0 * N + col;
#pragma unroll 4
    for (int i = 0; i < 32; i++) {
        float u = us[i];
        uint2 dr = ldK8(Kp + (size_t)i * N, pol);
        float2 f0 = __bfloat1622float2(*reinterpret_cast<__nv_bfloat162*>(&dr.x));
        float2 f1 = __bfloat1622float2(*reinterpret_cast<__nv_bfloat162*>(&dr.y));
        a0 += f0.x * u; a1 += f0.y * u;
        a2 += f1.x * u; a3 += f1.y * u;
    }
    *(float4*)&g_zp[(size_t)rb * N + col] = make_float4(a0, a1, a2, a3);
}

// ---- v = b / (sum_b z_b + stab) ----
__global__ void fin_kernel() {
    int j = blockIdx.x * 256 + threadIdx.x;
    float s = 0.f;
#pragma unroll 8
    for (int k = 0; k < 128; k++) s += g_zp[(size_t)k * N + j];
    g_v[j] = (1.0f / N) / (s + 1e-8f);
}

// ---- coupling = u * exp(-C/8) * v ; per-row loss partials (scalar: +1 offset) ----
__global__ void final_kernel(float* __restrict__ out) {
    int row = blockIdx.x, tid = threadIdx.x;
    float u = g_u[row];
    const float* Crow = out + OUT_C + (size_t)row * N;
    float* Prow = out + OUT_P + (size_t)row * N;
    float ls = 0.f;
#pragma unroll 4
    for (int s = 0; s < 16; s++) {
        int j = s * 256 + tid;
        float C = __ldcs(Crow + j);
        float cp = u * __expf(-0.125f * C) * g_v[j];
        __stcs(Prow + j, cp);
        ls += cp * C;
    }
    __shared__ float red[256];
    red[tid] = ls;
    __syncthreads();
    for (int o = 128; o > 0; o >>= 1) {
        if (tid < o) red[tid] += red[tid + o];
        __syncthreads();
    }
    if (tid == 0) g_part[row] = red[0];
}

__global__ void loss_kernel(float* __restrict__ out) {
    int tid = threadIdx.x;
    float s = 0.f;
#pragma unroll
    for (int q = 0; q < 16; q++) s += g_part[tid + q * 256];
    __shared__ float red[256];
    red[tid] = s;
    __syncthreads();
    for (int o = 128; o > 0; o >>= 1) {
        if (tid < o) red[tid] += red[tid + o];
        __syncthreads();
    }
    if (tid == 0) out[0] = red[0] * (1.0f / ((float)N * (float)N));
}

extern "C" void kernel_launch(void* const* d_in, const int* in_sizes, int n_in,
                              void* d_out, int out_size) {
    const float* S  = (const float*)d_in[0];
    const float* Tm = (const float*)d_in[1];
    float* out = (float*)d_out;

    __nv_bfloat16 *dSb, *dTb;
    float *dSn, *dTn;
    cudaGetSymbolAddress((void**)&dSb, g_Sb);
    cudaGetSymbolAddress((void**)&dTb, g_Tb);
    cudaGetSymbolAddress((void**)&dSn, g_sn);
    cudaGetSymbolAddress((void**)&dTn, g_tn);

    init_kernel<<<16, 256>>>();
    cvt_norm_kernel<<<2048, 256>>>(S, dSb, dSn);
    cvt_norm_kernel<<<2048, 256>>>(Tm, dTb, dTn);
    gemm_kernel<<<dim3(32, 32), 256>>>(out);
    for (int it = 0; it < 10; it++) {
        row_kernel<<<1024, 256>>>();
        col_kernel<<<512, 256>>>();
        fin_kernel<<<16, 256>>>();
    }
    final_kernel<<<4096, 256>>>(out);
    loss_kernel<<<1, 256>>>(out);
}